// round 17
// baseline (speedup 1.0000x reference)
#include <cuda_runtime.h>
#include <cstdint>
#include <math.h>

#define T_TOKENS 8192
#define NEXP     64
#define KDIM     4096
#define TOPK     8

#define TM       64                   // tokens per CTA
#define KC       64                   // K per stage
#define NSTAGES  (KDIM / KC)          // 64
#define NTHREADS 512                  // 16 warps: 2 K-groups x 8 MMA warps
#define GRID     (T_TOKENS / TM)      // 128 CTAs (1 wave)

#define ROWW       66                 // words per packed row (64 + 2 pad, even -> 8B aligned pairs)
#define TILE_WORDS (64 * ROWW)
#define BUF_WORDS  (4 * TILE_WORDS)   // Ah, Al, Bh, Bl
#define SMEM_BYTES (2 * BUF_WORDS * 4)
#define LROW       66                 // logits row stride (reuse smem)

// Deterministic aux-loss partials + completion counter (zero-init, reset each launch)
__device__ float g_psum[GRID * NEXP];
__device__ int   g_cnt [GRID * NEXP];
__device__ int   g_done;

// packed addr: pairs (k, k+4) adjacent so {b0,b1}/{a0,a2} are one 64-bit LDS
__device__ __forceinline__ int paddr(int row, int k) {
    return row * ROWW + ((k >> 3) << 3) + ((k & 3) << 1) + ((k >> 2) & 1);
}

__device__ __forceinline__ void tf32split(float x, uint32_t& hi, uint32_t& lo) {
    uint32_t xb = __float_as_uint(x);
    hi = xb & 0xFFFFE000u;
    float r = __fsub_rn(x, __uint_as_float(hi));
    lo = __float_as_uint(r) & 0xFFFFE000u;
}

__device__ __forceinline__ void mma_tf32(float* c, const uint32_t* a, uint32_t b0, uint32_t b1) {
    asm volatile(
        "mma.sync.aligned.m16n8k8.row.col.f32.tf32.tf32.f32 "
        "{%0,%1,%2,%3}, {%4,%5,%6,%7}, {%8,%9}, {%0,%1,%2,%3};"
        : "+f"(c[0]), "+f"(c[1]), "+f"(c[2]), "+f"(c[3])
        : "r"(a[0]), "r"(a[1]), "r"(a[2]), "r"(a[3]), "r"(b0), "r"(b1));
}

__device__ __forceinline__ void store_split4(uint32_t* th, uint32_t* tl,
                                             int row, int c4, float4 v) {
    uint32_t hi, lo;
    const int k = c4 * 4;
    tf32split(v.x, hi, lo); th[paddr(row, k+0)] = hi; tl[paddr(row, k+0)] = lo;
    tf32split(v.y, hi, lo); th[paddr(row, k+1)] = hi; tl[paddr(row, k+1)] = lo;
    tf32split(v.z, hi, lo); th[paddr(row, k+2)] = hi; tl[paddr(row, k+2)] = lo;
    tf32split(v.w, hi, lo); th[paddr(row, k+3)] = hi; tl[paddr(row, k+3)] = lo;
}

// -----------------------------------------------------------------------------
__global__ __launch_bounds__(NTHREADS, 1) void router_kernel(
    const float* __restrict__ H,   // [8192, 4096]
    const float* __restrict__ G,   // [64, 4096]
    float* __restrict__ out)       // [65536 w | 65536 idx | 1 loss]
{
    extern __shared__ uint32_t smem[];
    __shared__ int s_cnt[NEXP];
    __shared__ int s_isLast;
    __shared__ float fps[8][NEXP];
    __shared__ int   fct[8][NEXP];
    __shared__ float ffp[NEXP];

    const int tid  = threadIdx.x;
    const int warp = tid >> 5;
    const int lane = tid & 31;
    const int grp  = warp >> 3;          // 0..1 : K-group (chunks 4g..4g+3)
    const int w8   = warp & 7;
    const int mw   = w8 >> 1;            // 0..3 : rows mw*16
    const int nw   = w8 & 1;             // 0..1 : cols nw*32
    const int g    = lane >> 2;          // 0..7
    const int t    = lane & 3;           // 0..3
    const int m0   = blockIdx.x * TM;

    if (tid < NEXP) s_cnt[tid] = 0;

    // per-thread fill mapping: 2 float4 of H, 2 of G per stage
    int rowF[2], c4F[2];
#pragma unroll
    for (int i = 0; i < 2; i++) {
        const int idx4 = tid + i * NTHREADS;   // < 1024
        rowF[i] = idx4 >> 4;
        c4F[i]  = idx4 & 15;
    }

    // ---- prologue: fill stage 0 into buffer 0 ----
    {
        uint32_t* Ah = smem;
        uint32_t* Al = smem + TILE_WORDS;
        uint32_t* Bh = smem + 2 * TILE_WORDS;
        uint32_t* Bl = smem + 3 * TILE_WORDS;
#pragma unroll
        for (int i = 0; i < 2; i++) {
            float4 v = *(const float4*)(H + (size_t)(m0 + rowF[i]) * KDIM + c4F[i] * 4);
            store_split4(Ah, Al, rowF[i], c4F[i], v);
            float4 u = *(const float4*)(G + (size_t)rowF[i] * KDIM + c4F[i] * 4);
            store_split4(Bh, Bl, rowF[i], c4F[i], u);
        }
    }
    __syncthreads();

    float C[4][4], M[4][4], CK[4][4];
#pragma unroll
    for (int T = 0; T < 4; T++)
#pragma unroll
        for (int i = 0; i < 4; i++) { C[T][i] = 0.0f; M[T][i] = 0.0f; CK[T][i] = 0.0f; }

    const int aBase0 = (mw * 16 + g) * ROWW;
    const int aBase1 = aBase0 + 8 * ROWW;
    const int bBase  = (nw * 32 + g) * ROWW;

    float4 hreg[2], greg[2];

    for (int st = 0; st < NSTAGES; st++) {
        const int cur = st & 1;
        const uint32_t* bufc = smem + cur * BUF_WORDS;

        if (st + 1 < NSTAGES) {   // prefetch next stage into registers
            const int koff = (st + 1) * KC;
#pragma unroll
            for (int i = 0; i < 2; i++) {
                hreg[i] = *(const float4*)(H + (size_t)(m0 + rowF[i]) * KDIM + koff + c4F[i] * 4);
                greg[i] = *(const float4*)(G + (size_t)rowF[i] * KDIM + koff + c4F[i] * 4);
            }
        }

        // ---- compute: this group's 4 k8-chunks ----
        const uint32_t* Ah = bufc;
        const uint32_t* Al = bufc + TILE_WORDS;
        const uint32_t* Bh = bufc + 2 * TILE_WORDS;
        const uint32_t* Bl = bufc + 3 * TILE_WORDS;
#pragma unroll
        for (int c8 = 0; c8 < 4; c8++) {
            const int ch = grp * 4 + c8;
            const int co = ch * 8 + t * 2;
            uint32_t aH[4], aL[4];
            {
                const uint2 p0 = *(const uint2*)(Ah + aBase0 + co);
                const uint2 p1 = *(const uint2*)(Ah + aBase1 + co);
                aH[0] = p0.x; aH[2] = p0.y; aH[1] = p1.x; aH[3] = p1.y;
                const uint2 q0 = *(const uint2*)(Al + aBase0 + co);
                const uint2 q1 = *(const uint2*)(Al + aBase1 + co);
                aL[0] = q0.x; aL[2] = q0.y; aL[1] = q1.x; aL[3] = q1.y;
            }
#pragma unroll
            for (int T = 0; T < 4; T++) {
                const int bo = bBase + T * 8 * ROWW + co;
                const uint2 bh = *(const uint2*)(Bh + bo);
                const uint2 bl = *(const uint2*)(Bl + bo);
                mma_tf32(C[T], aH, bh.x, bh.y);   // hh
                mma_tf32(C[T], aH, bl.x, bl.y);   // hl
                mma_tf32(C[T], aL, bh.x, bh.y);   // lh
            }
        }

        // Kahan-fold stage partial into masters every stage (short chains)
#pragma unroll
        for (int T = 0; T < 4; T++)
#pragma unroll
            for (int i = 0; i < 4; i++) {
                const float y = __fsub_rn(C[T][i], CK[T][i]);
                const float u = __fadd_rn(M[T][i], y);
                CK[T][i] = __fsub_rn(__fsub_rn(u, M[T][i]), y);
                M[T][i] = u;
                C[T][i] = 0.0f;
            }

        if (st + 1 < NSTAGES) {
            uint32_t* nb = smem + (cur ^ 1) * BUF_WORDS;
#pragma unroll
            for (int i = 0; i < 2; i++) {
                store_split4(nb, nb + TILE_WORDS, rowF[i], c4F[i], hreg[i]);
                store_split4(nb + 2 * TILE_WORDS, nb + 3 * TILE_WORDS, rowF[i], c4F[i], greg[i]);
            }
        }
        __syncthreads();
    }

    // ---- merge groups + scatter to smem logits [64][LROW] ----
    float* logits = (float*)smem;
    const int r0 = mw * 16 + g;
    const int r1 = r0 + 8;
    if (grp == 0) {
#pragma unroll
        for (int T = 0; T < 4; T++) {
            const int cb = nw * 32 + T * 8 + 2 * t;
            logits[r0 * LROW + cb]     = M[T][0];
            logits[r0 * LROW + cb + 1] = M[T][1];
            logits[r1 * LROW + cb]     = M[T][2];
            logits[r1 * LROW + cb + 1] = M[T][3];
        }
    }
    __syncthreads();
    if (grp == 1) {
#pragma unroll
        for (int T = 0; T < 4; T++) {
            const int cb = nw * 32 + T * 8 + 2 * t;
            logits[r0 * LROW + cb]     = __fadd_rn(logits[r0 * LROW + cb],     M[T][0]);
            logits[r0 * LROW + cb + 1] = __fadd_rn(logits[r0 * LROW + cb + 1], M[T][1]);
            logits[r1 * LROW + cb]     = __fadd_rn(logits[r1 * LROW + cb],     M[T][2]);
            logits[r1 * LROW + cb + 1] = __fadd_rn(logits[r1 * LROW + cb + 1], M[T][3]);
        }
    }
    __syncthreads();

    // ---- fused epilogue: one thread per token ----
    if (tid < TM) {
        float row[NEXP];
        float mx = -1e30f;
#pragma unroll
        for (int e = 0; e < NEXP; e++) {
            row[e] = logits[tid * LROW + e];
            mx = fmaxf(mx, row[e]);
        }
        float s = 0.0f;
#pragma unroll
        for (int e = 0; e < NEXP; e++) { row[e] = expf(row[e] - mx); s += row[e]; }
        const float inv = 1.0f / s;
#pragma unroll
        for (int e = 0; e < NEXP; e++) {
            row[e] *= inv;
            logits[tid * LROW + e] = row[e];
        }

        // stable top-8 (descending, ties -> lower index)
        float pv = 3.4e38f; int pidx = -1;
        float w[TOPK]; int idx[TOPK]; float wsum = 0.0f;
#pragma unroll
        for (int j = 0; j < TOPK; j++) {
            float bv = -1.0f; int bidx = -1;
#pragma unroll
            for (int e = 0; e < NEXP; e++) {
                const float v = row[e];
                const bool elig   = (v < pv) || (v == pv && e > pidx);
                const bool better = (v > bv) || (v == bv && e < bidx);
                if (elig && better) { bv = v; bidx = e; }
            }
            w[j] = bv; idx[j] = bidx; wsum += bv;
            pv = bv; pidx = bidx;
        }
        const float invw = 1.0f / wsum;
        const size_t gm = (size_t)(m0 + tid) * TOPK;
#pragma unroll
        for (int j = 0; j < TOPK; j++) {
            out[gm + j] = w[j] * invw;
            out[(size_t)T_TOKENS * TOPK + gm + j] = (float)idx[j];
            atomicAdd(&s_cnt[idx[j]], 1);
        }
    }
    __syncthreads();

    // per-block aux partials, fixed order (deterministic)
    if (tid < NEXP) {
        const int e = tid;
        float ps = 0.0f;
        for (int m = 0; m < TM; m++) ps += logits[m * LROW + e];
        g_psum[blockIdx.x * NEXP + e] = ps;
        g_cnt [blockIdx.x * NEXP + e] = s_cnt[e];
    }

    // ---- last block finalizes the aux loss (single-kernel) ----
    __threadfence();
    __syncthreads();
    if (tid == 0) {
        const int v = atomicAdd(&g_done, 1);
        s_isLast = (v == GRID - 1);
    }
    __syncthreads();
    if (s_isLast) {
        __threadfence();
        const int e    = tid & (NEXP - 1);
        const int part = tid >> 6;          // 0..7, 16 blocks each
        float ps = 0.0f; int cnt = 0;
#pragma unroll 4
        for (int b = part * 16; b < part * 16 + 16; b++) {
            ps  += g_psum[b * NEXP + e];
            cnt += g_cnt [b * NEXP + e];
        }
        fps[part][e] = ps;
        fct[part][e] = cnt;
        __syncthreads();
        if (part == 0) {
            float tot = 0.0f; int ctt = 0;
#pragma unroll
            for (int p = 0; p < 8; p++) { tot += fps[p][e]; ctt += fct[p][e]; }
            const float f = (float)ctt / (float)(T_TOKENS * TOPK);
            const float p = tot / (float)T_TOKENS;
            ffp[e] = f * p;
        }
        __syncthreads();
        if (tid == 0) {
            float L = 0.0f;
#pragma unroll
            for (int i = 0; i < NEXP; i++) L += ffp[i];
            out[(size_t)T_TOKENS * TOPK * 2] = (float)NEXP * L;
            g_done = 0;   // reset for graph replay determinism
        }
    }
}

extern "C" void kernel_launch(void* const* d_in, const int* in_sizes, int n_in,
                              void* d_out, int out_size)
{
    const float* H = (const float*)d_in[0];
    const float* G = (const float*)d_in[1];
    float* out = (float*)d_out;
    cudaFuncSetAttribute(router_kernel, cudaFuncAttributeMaxDynamicSharedMemorySize, SMEM_BYTES);
    router_kernel<<<GRID, NTHREADS, SMEM_BYTES>>>(H, G, out);
}